// round 4
// baseline (speedup 1.0000x reference)
#include <cuda_runtime.h>
#include <cstdint>

// ---------------- problem constants ----------------
#define BBATCH 2
#define SS 2048
#define DM 1024
#define NH 16
#define DK 64
#define DFF 4096
#define NTOK (BBATCH*SS)                  // 4096
#define OUT_ELEMS ((long)NTOK*DM)         // 4,194,304

// ---------------- scratch (device globals, allocation-free) ----------------
__device__ float g_q  [NTOK*DM];
__device__ float g_k  [NTOK*DM];
__device__ float g_v  [NTOK*DM];
__device__ float g_vt [NTOK*DM];   // V transposed per batch: [B][DM][S]
__device__ float g_ctx[NTOK*DM];
__device__ float g_t0 [NTOK*DM];
__device__ float g_x1 [NTOK*DM];
__device__ float g_ff [NTOK*DFF];
__device__ float g_wqT[DM*DM];
__device__ float g_wkT[DM*DM];
__device__ float g_wvT[DM*DM];
__device__ float g_woT[DM*DM];
__device__ float g_w1T[DM*DFF];
__device__ float g_w2T[DM*DFF];

__device__ __forceinline__ uint32_t tf32r(float x){
    uint32_t r; asm("cvt.rna.tf32.f32 %0, %1;" : "=r"(r) : "f"(x)); return r;
}
__device__ __forceinline__ uint32_t smem_u32(const void* p){
    uint32_t a;
    asm("{ .reg .u64 t; cvta.to.shared.u64 t, %1; cvt.u32.u64 %0, t; }" : "=r"(a) : "l"(p));
    return a;
}
__device__ __forceinline__ void cpa16(uint32_t dst, const void* src){
    asm volatile("cp.async.cg.shared.global [%0], [%1], 16;" :: "r"(dst), "l"(src));
}
__device__ __forceinline__ void cpa_commit(){
    asm volatile("cp.async.commit_group;" ::: "memory");
}
template<int N>
__device__ __forceinline__ void cpa_wait(){
    asm volatile("cp.async.wait_group %0;" :: "n"(N) : "memory");
}

// ---------------------------------------------------------------------------
// tf32 mma.sync GEMM: C[M,N] = alpha * A[M,K] * B[N,K]^T + bias (+ReLU)
// A,B K-major fp32 in gmem. cp.async 3-stage pipeline into padded smem
// (raw fp32); cvt.rna.tf32 applied at fragment load.
// CTA tile 128 x BN, 256 threads (8 warps), warp tile 32 x (BN/2), BK=16.
// Batched via blockIdx.z (zb=z>>4, zh=z&15) strides.
// ---------------------------------------------------------------------------
template<int BN>
__global__ void __launch_bounds__(256)
tc_gemm(const float* __restrict__ A, const float* __restrict__ B,
        const float* __restrict__ bias, float* __restrict__ C,
        int K, int lda, int ldb, int ldc,
        long sA_b, long sA_h, long sB_b, long sB_h, long sC_b, long sC_h,
        float alpha, int relu)
{
    constexpr int BK   = 16;
    constexpr int LDSP = 20;          // pitch (floats): ≡4 mod 32 -> conflict-free; 80B rows keep 16B align
    constexpr int ST   = 3;           // pipeline stages
    constexpr int WN   = BN/2;        // 64 or 32
    constexpr int NT   = WN/8;        // 8 or 4
    constexpr int AIT  = 2;           // 128 rows*4 segs / 256 thr
    constexpr int BIT  = BN/64;       // 2 or 1
    constexpr int ASTG = 128*LDSP;    // floats per A stage
    constexpr int BSTG = BN*LDSP;

    extern __shared__ float sm[];
    float* AsBase = sm;                    // [ST][ASTG]
    float* BsBase = sm + ST*ASTG;          // [ST][BSTG]
    const uint32_t aU = smem_u32(AsBase);
    const uint32_t bU = smem_u32(BsBase);

    const int tid = threadIdx.x, wid = tid>>5, lane = tid&31;
    { int z = blockIdx.z, zb = z>>4, zh = z&15;
      A += zb*sA_b + zh*sA_h; B += zb*sB_b + zh*sB_h; C += zb*sC_b + zh*sC_h; }
    const int m0 = blockIdx.y*128, n0 = blockIdx.x*BN;
    A += (long)m0*lda;
    B += (long)n0*ldb;

    const int wm = (wid>>1)*32, wn = (wid&1)*WN;
    const int r4 = lane>>2, c4 = lane&3;

    float acc[2][NT][4];
    #pragma unroll
    for (int i = 0; i < 2; i++)
        #pragma unroll
        for (int j = 0; j < NT; j++)
            #pragma unroll
            for (int q = 0; q < 4; q++) acc[i][j][q] = 0.f;

    const int nch = K / BK;

    // ---- prologue: fill ST-1 stages ----
    #pragma unroll
    for (int s = 0; s < ST-1; s++){
        if (s < nch){
            const int k0 = s*BK;
            #pragma unroll
            for (int i = 0; i < AIT; i++){
                int idx = i*256 + tid, r = idx>>2, sg = idx&3;
                cpa16(aU + (s*ASTG + r*LDSP + sg*4)*4, A + (long)r*lda + k0 + sg*4);
            }
            #pragma unroll
            for (int i = 0; i < BIT; i++){
                int idx = i*256 + tid, r = idx>>2, sg = idx&3;
                cpa16(bU + (s*BSTG + r*LDSP + sg*4)*4, B + (long)r*ldb + k0 + sg*4);
            }
        }
        cpa_commit();
    }

    for (int c = 0; c < nch; c++){
        cpa_wait<ST-2>();
        __syncthreads();

        // issue loads for chunk c+ST-1 into stage (c+ST-1)%ST  (== (c-1)%ST slot)
        if (c + ST-1 < nch){
            const int s = (c + ST-1) % ST;
            const int k0 = (c + ST-1)*BK;
            #pragma unroll
            for (int i = 0; i < AIT; i++){
                int idx = i*256 + tid, r = idx>>2, sg = idx&3;
                cpa16(aU + (s*ASTG + r*LDSP + sg*4)*4, A + (long)r*lda + k0 + sg*4);
            }
            #pragma unroll
            for (int i = 0; i < BIT; i++){
                int idx = i*256 + tid, r = idx>>2, sg = idx&3;
                cpa16(bU + (s*BSTG + r*LDSP + sg*4)*4, B + (long)r*ldb + k0 + sg*4);
            }
        }
        cpa_commit();

        const float* as = AsBase + (c % ST)*ASTG;
        const float* bs = BsBase + (c % ST)*BSTG;

        #pragma unroll
        for (int ks = 0; ks < 2; ks++){
            uint32_t bf[NT][2];
            #pragma unroll
            for (int nj = 0; nj < NT; nj++){
                const float* bp = bs + (wn + nj*8 + r4)*LDSP + ks*8 + c4;
                bf[nj][0] = tf32r(bp[0]);
                bf[nj][1] = tf32r(bp[4]);
            }
            #pragma unroll
            for (int mi = 0; mi < 2; mi++){
                const float* ap = as + (wm + mi*16 + r4)*LDSP + ks*8 + c4;
                uint32_t a0 = tf32r(ap[0]);
                uint32_t a1 = tf32r(ap[8*LDSP]);
                uint32_t a2 = tf32r(ap[4]);
                uint32_t a3 = tf32r(ap[8*LDSP + 4]);
                #pragma unroll
                for (int nj = 0; nj < NT; nj++){
                    asm("mma.sync.aligned.m16n8k8.row.col.f32.tf32.tf32.f32 "
                        "{%0,%1,%2,%3}, {%4,%5,%6,%7}, {%8,%9}, {%0,%1,%2,%3};"
                        : "+f"(acc[mi][nj][0]), "+f"(acc[mi][nj][1]),
                          "+f"(acc[mi][nj][2]), "+f"(acc[mi][nj][3])
                        : "r"(a0), "r"(a1), "r"(a2), "r"(a3),
                          "r"(bf[nj][0]), "r"(bf[nj][1]));
                }
            }
        }
    }

    // ---- epilogue: accumulators in registers ----
    #pragma unroll
    for (int mi = 0; mi < 2; mi++){
        const int row0 = m0 + wm + mi*16 + r4;
        #pragma unroll
        for (int nj = 0; nj < NT; nj++){
            const int col = n0 + wn + nj*8 + c4*2;
            float b0 = 0.f, b1 = 0.f;
            if (bias){ b0 = __ldg(&bias[col]); b1 = __ldg(&bias[col+1]); }
            float v0 = acc[mi][nj][0]*alpha + b0;
            float v1 = acc[mi][nj][1]*alpha + b1;
            float v2 = acc[mi][nj][2]*alpha + b0;
            float v3 = acc[mi][nj][3]*alpha + b1;
            if (relu){
                v0 = fmaxf(v0,0.f); v1 = fmaxf(v1,0.f);
                v2 = fmaxf(v2,0.f); v3 = fmaxf(v3,0.f);
            }
            float2 p0 = {v0, v1}, p1 = {v2, v3};
            *(float2*)&C[(long)row0*ldc + col]      = p0;
            *(float2*)&C[(long)(row0+8)*ldc + col]  = p1;
        }
    }
}

// ---------------------------------------------------------------------------
// Tiled transpose: out[c*R + r] = in[r*C + c], batched via blockIdx.z.
// ---------------------------------------------------------------------------
__global__ void transpose_k(const float* __restrict__ in, float* __restrict__ out,
                            int R, int C)
{
    __shared__ float t[32][33];
    const long zoff = (long)blockIdx.z * R * C;
    in += zoff; out += zoff;
    const int c0 = blockIdx.x*32, r0 = blockIdx.y*32;
    #pragma unroll
    for (int i = threadIdx.y; i < 32; i += 8)
        t[i][threadIdx.x] = in[(long)(r0+i)*C + c0 + threadIdx.x];
    __syncthreads();
    #pragma unroll
    for (int i = threadIdx.y; i < 32; i += 8)
        out[(long)(c0+i)*R + r0 + threadIdx.x] = t[threadIdx.x][i];
}

// ---------------------------------------------------------------------------
// Row softmax in-place over [rows, 2048]; 256 threads per row.
// ---------------------------------------------------------------------------
__global__ void softmax_k(float* __restrict__ attn)
{
    const long row = blockIdx.x;
    float4* p = (float4*)(attn + row * (long)SS);
    const int t = threadIdx.x;
    float4 a = p[t];
    float4 b = p[t + 256];

    __shared__ float red[256];
    float m = fmaxf(fmaxf(fmaxf(a.x,a.y),fmaxf(a.z,a.w)),
                    fmaxf(fmaxf(b.x,b.y),fmaxf(b.z,b.w)));
    red[t] = m; __syncthreads();
    for (int s = 128; s > 0; s >>= 1){
        if (t < s) red[t] = fmaxf(red[t], red[t+s]);
        __syncthreads();
    }
    const float mx = red[0]; __syncthreads();

    a.x = expf(a.x-mx); a.y = expf(a.y-mx); a.z = expf(a.z-mx); a.w = expf(a.w-mx);
    b.x = expf(b.x-mx); b.y = expf(b.y-mx); b.z = expf(b.z-mx); b.w = expf(b.w-mx);

    red[t] = a.x+a.y+a.z+a.w + b.x+b.y+b.z+b.w; __syncthreads();
    for (int s = 128; s > 0; s >>= 1){
        if (t < s) red[t] += red[t+s];
        __syncthreads();
    }
    const float inv = 1.f / red[0];
    a.x*=inv; a.y*=inv; a.z*=inv; a.w*=inv;
    b.x*=inv; b.y*=inv; b.z*=inv; b.w*=inv;
    p[t] = a; p[t+256] = b;
}

// ---------------------------------------------------------------------------
// out = LayerNorm(a + r)*gamma + beta; 256 threads per token row (D=1024).
// ---------------------------------------------------------------------------
__global__ void add_ln_k(const float* __restrict__ a, const float* __restrict__ r,
                         const float* __restrict__ g, const float* __restrict__ be,
                         float* __restrict__ o)
{
    const long row = blockIdx.x;
    const int t = threadIdx.x;
    float4 x = ((const float4*)(a + row*DM))[t];
    float4 y = ((const float4*)(r + row*DM))[t];
    x.x += y.x; x.y += y.y; x.z += y.z; x.w += y.w;

    __shared__ float rs[256], rq[256];
    rs[t] = x.x+x.y+x.z+x.w;
    rq[t] = x.x*x.x + x.y*x.y + x.z*x.z + x.w*x.w;
    __syncthreads();
    for (int s = 128; s > 0; s >>= 1){
        if (t < s){ rs[t] += rs[t+s]; rq[t] += rq[t+s]; }
        __syncthreads();
    }
    const float mu  = rs[0] * (1.f/DM);
    const float var = rq[0] * (1.f/DM) - mu*mu;
    const float rst = rsqrtf(var + 1e-5f);

    float4 gg = ((const float4*)g)[t];
    float4 bb = ((const float4*)be)[t];
    float4 out;
    out.x = (x.x-mu)*rst*gg.x + bb.x;
    out.y = (x.y-mu)*rst*gg.y + bb.y;
    out.z = (x.z-mu)*rst*gg.z + bb.z;
    out.w = (x.w-mu)*rst*gg.w + bb.w;
    ((float4*)(o + row*DM))[t] = out;
}

// ---------------------------------------------------------------------------

extern "C" void kernel_launch(void* const* d_in, const int* in_sizes, int n_in,
                              void* d_out, int out_size)
{
    const float* src = (const float*)d_in[0];
    const float* wq  = (const float*)d_in[1];
    const float* bq  = (const float*)d_in[2];
    const float* wk  = (const float*)d_in[3];
    const float* bk  = (const float*)d_in[4];
    const float* wv  = (const float*)d_in[5];
    const float* bv  = (const float*)d_in[6];
    const float* wo  = (const float*)d_in[7];
    const float* bo  = (const float*)d_in[8];
    const float* w1  = (const float*)d_in[9];
    const float* b1  = (const float*)d_in[10];
    const float* w2  = (const float*)d_in[11];
    const float* b2  = (const float*)d_in[12];
    const float* g1  = (const float*)d_in[13];
    const float* be1 = (const float*)d_in[14];
    const float* g2  = (const float*)d_in[15];
    const float* be2 = (const float*)d_in[16];

    float* outp  = (float*)d_out;
    float* attnp = (float*)d_out + OUT_ELEMS;

    float *q,*k,*v,*vt,*ctx,*t0,*x1,*ff,*wqT,*wkT,*wvT,*woT,*w1T,*w2T;
    cudaGetSymbolAddress((void**)&q,   g_q);
    cudaGetSymbolAddress((void**)&k,   g_k);
    cudaGetSymbolAddress((void**)&v,   g_v);
    cudaGetSymbolAddress((void**)&vt,  g_vt);
    cudaGetSymbolAddress((void**)&ctx, g_ctx);
    cudaGetSymbolAddress((void**)&t0,  g_t0);
    cudaGetSymbolAddress((void**)&x1,  g_x1);
    cudaGetSymbolAddress((void**)&ff,  g_ff);
    cudaGetSymbolAddress((void**)&wqT, g_wqT);
    cudaGetSymbolAddress((void**)&wkT, g_wkT);
    cudaGetSymbolAddress((void**)&wvT, g_wvT);
    cudaGetSymbolAddress((void**)&woT, g_woT);
    cudaGetSymbolAddress((void**)&w1T, g_w1T);
    cudaGetSymbolAddress((void**)&w2T, g_w2T);

    const int SM128 = 3*(128*20 + 128*20)*4;   // 61440
    const int SM64  = 3*(128*20 +  64*20)*4;   // 46080
    cudaFuncSetAttribute(tc_gemm<128>, cudaFuncAttributeMaxDynamicSharedMemorySize, SM128);
    cudaFuncSetAttribute(tc_gemm<64>,  cudaFuncAttributeMaxDynamicSharedMemorySize, SM64);

    // ---- 0) transpose weights to [N,K] K-major ----
    {
        dim3 b(32,8);
        transpose_k<<<dim3(32,32,1),  b>>>(wq, wqT, DM, DM);
        transpose_k<<<dim3(32,32,1),  b>>>(wk, wkT, DM, DM);
        transpose_k<<<dim3(32,32,1),  b>>>(wv, wvT, DM, DM);
        transpose_k<<<dim3(32,32,1),  b>>>(wo, woT, DM, DM);
        transpose_k<<<dim3(128,32,1), b>>>(w1, w1T, DM, DFF);   // -> [4096,1024]
        transpose_k<<<dim3(32,128,1), b>>>(w2, w2T, DFF, DM);   // -> [1024,4096]
    }

    // ---- 1) QKV projections ----
    {
        dim3 grid(DM/128, NTOK/128, 1);
        tc_gemm<128><<<grid,256,SM128>>>(src, wqT, bq, q, DM, DM, DM, DM,
                                         0,0,0,0,0,0, 1.f, 0);
        tc_gemm<128><<<grid,256,SM128>>>(src, wkT, bk, k, DM, DM, DM, DM,
                                         0,0,0,0,0,0, 1.f, 0);
        tc_gemm<128><<<grid,256,SM128>>>(src, wvT, bv, v, DM, DM, DM, DM,
                                         0,0,0,0,0,0, 1.f, 0);
    }

    // ---- 2) scores = Q K^T / 8 -> attn output region ----
    {
        dim3 grid(SS/128, SS/128, BBATCH*NH);
        tc_gemm<128><<<grid,256,SM128>>>(q, k, nullptr, attnp, DK, DM, DM, SS,
                                         (long)SS*DM, DK,
                                         (long)SS*DM, DK,
                                         (long)NH*SS*SS, (long)SS*SS,
                                         0.125f, 0);
    }

    // ---- 3) softmax in-place ----
    softmax_k<<<BBATCH*NH*SS, 256>>>(attnp);

    // ---- 4) V transpose per batch: [S,DM] -> [DM,S] ----
    transpose_k<<<dim3(DM/32, SS/32, BBATCH), dim3(32,8)>>>(v, vt, SS, DM);

    // ---- 5) ctx = P @ V ----
    {
        dim3 grid(1, SS/128, BBATCH*NH);
        tc_gemm<64><<<grid,256,SM64>>>(attnp, vt, nullptr, ctx, SS, SS, SS, DM,
                                       (long)NH*SS*SS, (long)SS*SS,
                                       (long)DM*SS, (long)DK*SS,
                                       (long)SS*DM, DK,
                                       1.f, 0);
    }

    // ---- 6) attn_out = ctx @ Wo + bo ----
    {
        dim3 grid(DM/128, NTOK/128, 1);
        tc_gemm<128><<<grid,256,SM128>>>(ctx, woT, bo, t0, DM, DM, DM, DM,
                                         0,0,0,0,0,0, 1.f, 0);
    }

    // ---- 7) x1 = LN(src + attn_out) ----
    add_ln_k<<<NTOK, 256>>>(src, t0, g1, be1, x1);

    // ---- 8) ff = relu(x1 @ W1 + b1) ----
    {
        dim3 grid(DFF/128, NTOK/128, 1);
        tc_gemm<128><<<grid,256,SM128>>>(x1, w1T, b1, ff, DM, DM, DM, DFF,
                                         0,0,0,0,0,0, 1.f, 1);
    }

    // ---- 9) t0 = ff @ W2 + b2 ----
    {
        dim3 grid(DM/128, NTOK/128, 1);
        tc_gemm<128><<<grid,256,SM128>>>(ff, w2T, b2, t0, DFF, DFF, DFF, DM,
                                         0,0,0,0,0,0, 1.f, 0);
    }

    // ---- 10) out = LN(x1 + t0) ----
    add_ln_k<<<NTOK, 256>>>(x1, t0, g2, be2, outp);
}

// round 5
// speedup vs baseline: 1.7672x; 1.7672x over previous
#include <cuda_runtime.h>
#include <cuda_fp16.h>
#include <cstdint>

// ---------------- problem constants ----------------
#define BBATCH 2
#define SS 2048
#define DM 1024
#define NH 16
#define DK 64
#define DFF 4096
#define NTOK (BBATCH*SS)                  // 4096
#define OUT_ELEMS ((long)NTOK*DM)         // 4,194,304
#define NROWS (BBATCH*NH*SS)              // 65536 attention rows

// ---------------- scratch (device globals, allocation-free) ----------------
__device__ __half g_srch[NTOK*DM];
__device__ __half g_qh  [NTOK*DM];
__device__ __half g_kh  [NTOK*DM];
__device__ __half g_vh  [NTOK*DM];
__device__ __half g_vth [NTOK*DM];           // V^T per batch: [B][DM][S]
__device__ __half g_E   [(long)BBATCH*NH*SS*SS];   // unnormalized exp(scores), 268 MB
__device__ __half g_ctxh[NTOK*DM];
__device__ __half g_x1h [NTOK*DM];
__device__ __half g_ffh [NTOK*DFF];
__device__ __half g_wqTh[DM*DM];
__device__ __half g_wkTh[DM*DM];
__device__ __half g_wvTh[DM*DM];
__device__ __half g_woTh[DM*DM];
__device__ __half g_w1Th[DM*DFF];
__device__ __half g_w2Th[DM*DFF];
__device__ float  g_t0 [NTOK*DM];
__device__ float  g_x1 [NTOK*DM];
__device__ float  g_rsum[NROWS];

__device__ __forceinline__ uint32_t smem_u32(const void* p){
    uint32_t a;
    asm("{ .reg .u64 t; cvta.to.shared.u64 t, %1; cvt.u32.u64 %0, t; }" : "=r"(a) : "l"(p));
    return a;
}
__device__ __forceinline__ void cpa16(uint32_t dst, const void* src){
    asm volatile("cp.async.cg.shared.global [%0], [%1], 16;" :: "r"(dst), "l"(src));
}
__device__ __forceinline__ void cpa_commit(){
    asm volatile("cp.async.commit_group;" ::: "memory");
}
template<int N>
__device__ __forceinline__ void cpa_wait(){
    asm volatile("cp.async.wait_group %0;" :: "n"(N) : "memory");
}

// ---------------------------------------------------------------------------
// fp16 mma.sync GEMM:  acc = A[M,K] * B[N,K]^T  (both K-major fp16)
// CTA tile 128 x BN, 256 threads, warp tile 32 x (BN/2), BK=32 halfs, 3-stage
// cp.async pipeline. Batched via blockIdx.z (zb=z>>4, zh=z&15).
// MODE 0: C fp32 = acc*alpha + bias (+relu)
// MODE 1: C fp16 = acc*alpha + bias (+relu)
// MODE 2: C fp16 = exp(acc*alpha); atomicAdd per-row sums into rsum[z*SS+row]
// MODE 3: C fp16 = acc * (1/rsum[z*SS+row])
// ---------------------------------------------------------------------------
template<int BN, int MODE>
__global__ void __launch_bounds__(256)
hgemm(const __half* __restrict__ A, const __half* __restrict__ B,
      const float* __restrict__ bias, void* __restrict__ Cv,
      float* __restrict__ rsum,
      int K, int lda, int ldb, int ldc,
      long sA_b, long sA_h, long sB_b, long sB_h, long sC_b, long sC_h,
      float alpha, int relu)
{
    constexpr int BKH  = 32;           // k halfs per chunk (2 mma k-steps)
    constexpr int LDH  = 40;           // pitch in halfs (20 words ≡ 4 mod 32 -> conflict-free)
    constexpr int ST   = 3;
    constexpr int WN   = BN/2;
    constexpr int NT   = WN/8;
    constexpr int AIT  = 2;            // 128 rows * 4 segs / 256 thr
    constexpr int BIT  = BN/64;
    constexpr int ASTG = 128*LDH;      // halfs per A stage
    constexpr int BSTG = BN*LDH;

    extern __shared__ __half hs[];
    const uint32_t aU = smem_u32(hs);
    const uint32_t bU = smem_u32(hs + ST*ASTG);

    const int tid = threadIdx.x, wid = tid>>5, lane = tid&31;
    const int z = blockIdx.z;
    { int zb = z>>4, zh = z&15;
      A += zb*sA_b + zh*sA_h; B += zb*sB_b + zh*sB_h; }
    const int m0 = blockIdx.y*128, n0 = blockIdx.x*BN;
    A += (long)m0*lda;
    B += (long)n0*ldb;

    const int wm = (wid>>1)*32, wn = (wid&1)*WN;
    const int r4 = lane>>2, c4 = lane&3;

    float acc[2][NT][4];
    #pragma unroll
    for (int i = 0; i < 2; i++)
        #pragma unroll
        for (int j = 0; j < NT; j++)
            #pragma unroll
            for (int q = 0; q < 4; q++) acc[i][j][q] = 0.f;

    const int nch = K / BKH;

    #pragma unroll
    for (int s = 0; s < ST-1; s++){
        if (s < nch){
            const int k0 = s*BKH;
            #pragma unroll
            for (int i = 0; i < AIT; i++){
                int idx = i*256 + tid, r = idx>>2, sg = idx&3;
                cpa16(aU + (s*ASTG + r*LDH + sg*8)*2, A + (long)r*lda + k0 + sg*8);
            }
            #pragma unroll
            for (int i = 0; i < BIT; i++){
                int idx = i*256 + tid, r = idx>>2, sg = idx&3;
                cpa16(bU + (s*BSTG + r*LDH + sg*8)*2, B + (long)r*ldb + k0 + sg*8);
            }
        }
        cpa_commit();
    }

    for (int c = 0; c < nch; c++){
        cpa_wait<ST-2>();
        __syncthreads();

        if (c + ST-1 < nch){
            const int s = (c + ST-1) % ST;
            const int k0 = (c + ST-1)*BKH;
            #pragma unroll
            for (int i = 0; i < AIT; i++){
                int idx = i*256 + tid, r = idx>>2, sg = idx&3;
                cpa16(aU + (s*ASTG + r*LDH + sg*8)*2, A + (long)r*lda + k0 + sg*8);
            }
            #pragma unroll
            for (int i = 0; i < BIT; i++){
                int idx = i*256 + tid, r = idx>>2, sg = idx&3;
                cpa16(bU + (s*BSTG + r*LDH + sg*8)*2, B + (long)r*ldb + k0 + sg*8);
            }
        }
        cpa_commit();

        const uint32_t* aw = (const uint32_t*)(hs + (c % ST)*ASTG);
        const uint32_t* bw = (const uint32_t*)(hs + ST*ASTG + (c % ST)*BSTG);

        #pragma unroll
        for (int ks = 0; ks < 2; ks++){
            uint32_t bf[NT][2];
            #pragma unroll
            for (int nj = 0; nj < NT; nj++){
                const uint32_t* bp = bw + (wn + nj*8 + r4)*20 + ks*8 + c4;
                bf[nj][0] = bp[0];
                bf[nj][1] = bp[4];
            }
            #pragma unroll
            for (int mi = 0; mi < 2; mi++){
                const uint32_t* ap = aw + (wm + mi*16 + r4)*20 + ks*8 + c4;
                uint32_t a0 = ap[0];
                uint32_t a1 = ap[160];     // +8 rows
                uint32_t a2 = ap[4];       // k + 8 halfs
                uint32_t a3 = ap[164];
                #pragma unroll
                for (int nj = 0; nj < NT; nj++){
                    asm("mma.sync.aligned.m16n8k16.row.col.f32.f16.f16.f32 "
                        "{%0,%1,%2,%3}, {%4,%5,%6,%7}, {%8,%9}, {%0,%1,%2,%3};"
                        : "+f"(acc[mi][nj][0]), "+f"(acc[mi][nj][1]),
                          "+f"(acc[mi][nj][2]), "+f"(acc[mi][nj][3])
                        : "r"(a0), "r"(a1), "r"(a2), "r"(a3),
                          "r"(bf[nj][0]), "r"(bf[nj][1]));
                }
            }
        }
    }

    // ------------------------- epilogues -------------------------
    if (MODE == 0){
        float* C = (float*)Cv + (long)(z>>4)*sC_b + (long)(z&15)*sC_h;
        #pragma unroll
        for (int mi = 0; mi < 2; mi++){
            const int row0 = m0 + wm + mi*16 + r4;
            #pragma unroll
            for (int nj = 0; nj < NT; nj++){
                const int col = n0 + wn + nj*8 + c4*2;
                float b0 = bias ? __ldg(&bias[col])   : 0.f;
                float b1 = bias ? __ldg(&bias[col+1]) : 0.f;
                float v0 = acc[mi][nj][0]*alpha + b0;
                float v1 = acc[mi][nj][1]*alpha + b1;
                float v2 = acc[mi][nj][2]*alpha + b0;
                float v3 = acc[mi][nj][3]*alpha + b1;
                if (relu){ v0=fmaxf(v0,0.f); v1=fmaxf(v1,0.f); v2=fmaxf(v2,0.f); v3=fmaxf(v3,0.f); }
                *(float2*)&C[(long)row0*ldc + col]     = make_float2(v0,v1);
                *(float2*)&C[(long)(row0+8)*ldc + col] = make_float2(v2,v3);
            }
        }
    } else if (MODE == 1){
        __half* C = (__half*)Cv + (long)(z>>4)*sC_b + (long)(z&15)*sC_h;
        #pragma unroll
        for (int mi = 0; mi < 2; mi++){
            const int row0 = m0 + wm + mi*16 + r4;
            #pragma unroll
            for (int nj = 0; nj < NT; nj++){
                const int col = n0 + wn + nj*8 + c4*2;
                float b0 = bias ? __ldg(&bias[col])   : 0.f;
                float b1 = bias ? __ldg(&bias[col+1]) : 0.f;
                float v0 = acc[mi][nj][0]*alpha + b0;
                float v1 = acc[mi][nj][1]*alpha + b1;
                float v2 = acc[mi][nj][2]*alpha + b0;
                float v3 = acc[mi][nj][3]*alpha + b1;
                if (relu){ v0=fmaxf(v0,0.f); v1=fmaxf(v1,0.f); v2=fmaxf(v2,0.f); v3=fmaxf(v3,0.f); }
                *(__half2*)&C[(long)row0*ldc + col]     = __floats2half2_rn(v0,v1);
                *(__half2*)&C[(long)(row0+8)*ldc + col] = __floats2half2_rn(v2,v3);
            }
        }
    } else if (MODE == 2){
        __half* C = (__half*)Cv + (long)(z>>4)*sC_b + (long)(z&15)*sC_h;
        float* rs = rsum + (long)z*SS;
        #pragma unroll
        for (int mi = 0; mi < 2; mi++){
            const int row0 = m0 + wm + mi*16 + r4;
            float p0 = 0.f, p1 = 0.f;
            #pragma unroll
            for (int nj = 0; nj < NT; nj++){
                const int col = n0 + wn + nj*8 + c4*2;
                float e0 = __expf(acc[mi][nj][0]*alpha);
                float e1 = __expf(acc[mi][nj][1]*alpha);
                float e2 = __expf(acc[mi][nj][2]*alpha);
                float e3 = __expf(acc[mi][nj][3]*alpha);
                p0 += e0 + e1;  p1 += e2 + e3;
                *(__half2*)&C[(long)row0*ldc + col]     = __floats2half2_rn(e0,e1);
                *(__half2*)&C[(long)(row0+8)*ldc + col] = __floats2half2_rn(e2,e3);
            }
            p0 += __shfl_xor_sync(0xffffffffu, p0, 1);
            p0 += __shfl_xor_sync(0xffffffffu, p0, 2);
            p1 += __shfl_xor_sync(0xffffffffu, p1, 1);
            p1 += __shfl_xor_sync(0xffffffffu, p1, 2);
            if (c4 == 0){
                atomicAdd(&rs[row0],     p0);
                atomicAdd(&rs[row0 + 8], p1);
            }
        }
    } else { // MODE 3
        __half* C = (__half*)Cv + (long)(z>>4)*sC_b + (long)(z&15)*sC_h;
        const float* rs = rsum + (long)z*SS;
        #pragma unroll
        for (int mi = 0; mi < 2; mi++){
            const int row0 = m0 + wm + mi*16 + r4;
            const float i0 = __fdividef(1.f, __ldg(&rs[row0]));
            const float i1 = __fdividef(1.f, __ldg(&rs[row0+8]));
            #pragma unroll
            for (int nj = 0; nj < NT; nj++){
                const int col = n0 + wn + nj*8 + c4*2;
                *(__half2*)&C[(long)row0*ldc + col] =
                    __floats2half2_rn(acc[mi][nj][0]*i0, acc[mi][nj][1]*i0);
                *(__half2*)&C[(long)(row0+8)*ldc + col] =
                    __floats2half2_rn(acc[mi][nj][2]*i1, acc[mi][nj][3]*i1);
            }
        }
    }
}

// ---------------------------------------------------------------------------
__global__ void zero_k(float* p){ p[blockIdx.x*1024 + threadIdx.x] = 0.f; }

__global__ void f2h_k(const float* __restrict__ in, __half* __restrict__ out){
    long i = ((long)blockIdx.x*256 + threadIdx.x)*4;
    float4 v = *(const float4*)(in + i);
    *(__half2*)(out + i)     = __floats2half2_rn(v.x, v.y);
    *(__half2*)(out + i + 2) = __floats2half2_rn(v.z, v.w);
}

// transpose fp32 -> fp16: out[c*R + r] = in[r*C + c]
__global__ void transpose_cvt(const float* __restrict__ in, __half* __restrict__ out,
                              int R, int C){
    __shared__ float t[32][33];
    const int c0 = blockIdx.x*32, r0 = blockIdx.y*32;
    #pragma unroll
    for (int i = threadIdx.y; i < 32; i += 8)
        t[i][threadIdx.x] = in[(long)(r0+i)*C + c0 + threadIdx.x];
    __syncthreads();
    #pragma unroll
    for (int i = threadIdx.y; i < 32; i += 8)
        out[(long)(c0+i)*R + r0 + threadIdx.x] = __float2half_rn(t[threadIdx.x][i]);
}

// transpose fp16 -> fp16, batched by blockIdx.z
__global__ void transpose_hh(const __half* __restrict__ in, __half* __restrict__ out,
                             int R, int C){
    __shared__ __half t[32][34];
    const long zoff = (long)blockIdx.z * R * C;
    in += zoff; out += zoff;
    const int c0 = blockIdx.x*32, r0 = blockIdx.y*32;
    #pragma unroll
    for (int i = threadIdx.y; i < 32; i += 8)
        t[i][threadIdx.x] = in[(long)(r0+i)*C + c0 + threadIdx.x];
    __syncthreads();
    #pragma unroll
    for (int i = threadIdx.y; i < 32; i += 8)
        out[(long)(c0+i)*R + r0 + threadIdx.x] = t[threadIdx.x][i];
}

// attn P (fp32, mandatory output) = E (fp16) / rowsum
__global__ void norm_attn(const __half* __restrict__ E, const float* __restrict__ rsum,
                          float* __restrict__ P){
    const long row = blockIdx.x;
    const __half2* e = (const __half2*)(E + row*(long)SS);
    float2* p = (float2*)(P + row*(long)SS);
    const float inv = __fdividef(1.f, __ldg(&rsum[row]));
    const int t = threadIdx.x;
    #pragma unroll
    for (int i = 0; i < 4; i++){
        float2 f = __half22float2(e[t + i*256]);
        f.x *= inv; f.y *= inv;
        p[t + i*256] = f;
    }
}

// x1 = LN(a + r); writes fp32 and (optionally) fp16
__global__ void add_ln_k(const float* __restrict__ a, const float* __restrict__ r,
                         const float* __restrict__ g, const float* __restrict__ be,
                         float* __restrict__ o, __half* __restrict__ oh)
{
    const long row = blockIdx.x;
    const int t = threadIdx.x;
    float4 x = ((const float4*)(a + row*DM))[t];
    float4 y = ((const float4*)(r + row*DM))[t];
    x.x += y.x; x.y += y.y; x.z += y.z; x.w += y.w;

    __shared__ float rs[256], rq[256];
    rs[t] = x.x+x.y+x.z+x.w;
    rq[t] = x.x*x.x + x.y*x.y + x.z*x.z + x.w*x.w;
    __syncthreads();
    for (int s = 128; s > 0; s >>= 1){
        if (t < s){ rs[t] += rs[t+s]; rq[t] += rq[t+s]; }
        __syncthreads();
    }
    const float mu  = rs[0] * (1.f/DM);
    const float var = rq[0] * (1.f/DM) - mu*mu;
    const float rst = rsqrtf(var + 1e-5f);

    float4 gg = ((const float4*)g)[t];
    float4 bb = ((const float4*)be)[t];
    float4 out;
    out.x = (x.x-mu)*rst*gg.x + bb.x;
    out.y = (x.y-mu)*rst*gg.y + bb.y;
    out.z = (x.z-mu)*rst*gg.z + bb.z;
    out.w = (x.w-mu)*rst*gg.w + bb.w;
    ((float4*)(o + row*DM))[t] = out;
    if (oh){
        *(__half2*)(oh + row*DM + t*4)     = __floats2half2_rn(out.x, out.y);
        *(__half2*)(oh + row*DM + t*4 + 2) = __floats2half2_rn(out.z, out.w);
    }
}

// ---------------------------------------------------------------------------

extern "C" void kernel_launch(void* const* d_in, const int* in_sizes, int n_in,
                              void* d_out, int out_size)
{
    const float* src = (const float*)d_in[0];
    const float* wq  = (const float*)d_in[1];
    const float* bq  = (const float*)d_in[2];
    const float* wk  = (const float*)d_in[3];
    const float* bk  = (const float*)d_in[4];
    const float* wv  = (const float*)d_in[5];
    const float* bv  = (const float*)d_in[6];
    const float* wo  = (const float*)d_in[7];
    const float* bo  = (const float*)d_in[8];
    const float* w1  = (const float*)d_in[9];
    const float* b1  = (const float*)d_in[10];
    const float* w2  = (const float*)d_in[11];
    const float* b2  = (const float*)d_in[12];
    const float* g1  = (const float*)d_in[13];
    const float* be1 = (const float*)d_in[14];
    const float* g2  = (const float*)d_in[15];
    const float* be2 = (const float*)d_in[16];

    float* outp  = (float*)d_out;
    float* attnp = (float*)d_out + OUT_ELEMS;

    __half *srch,*qh,*kh,*vh,*vth,*E,*ctxh,*x1h,*ffh,*wqTh,*wkTh,*wvTh,*woTh,*w1Th,*w2Th;
    float *t0,*x1,*rsum;
    cudaGetSymbolAddress((void**)&srch, g_srch);
    cudaGetSymbolAddress((void**)&qh,   g_qh);
    cudaGetSymbolAddress((void**)&kh,   g_kh);
    cudaGetSymbolAddress((void**)&vh,   g_vh);
    cudaGetSymbolAddress((void**)&vth,  g_vth);
    cudaGetSymbolAddress((void**)&E,    g_E);
    cudaGetSymbolAddress((void**)&ctxh, g_ctxh);
    cudaGetSymbolAddress((void**)&x1h,  g_x1h);
    cudaGetSymbolAddress((void**)&ffh,  g_ffh);
    cudaGetSymbolAddress((void**)&wqTh, g_wqTh);
    cudaGetSymbolAddress((void**)&wkTh, g_wkTh);
    cudaGetSymbolAddress((void**)&wvTh, g_wvTh);
    cudaGetSymbolAddress((void**)&woTh, g_woTh);
    cudaGetSymbolAddress((void**)&w1Th, g_w1Th);
    cudaGetSymbolAddress((void**)&w2Th, g_w2Th);
    cudaGetSymbolAddress((void**)&t0,   g_t0);
    cudaGetSymbolAddress((void**)&x1,   g_x1);
    cudaGetSymbolAddress((void**)&rsum, g_rsum);

    const int SM128 = 3*(128*40 + 128*40)*2;   // 61440
    const int SM64  = 3*(128*40 +  64*40)*2;   // 46080
    cudaFuncSetAttribute(hgemm<128,0>, cudaFuncAttributeMaxDynamicSharedMemorySize, SM128);
    cudaFuncSetAttribute(hgemm<128,1>, cudaFuncAttributeMaxDynamicSharedMemorySize, SM128);
    cudaFuncSetAttribute(hgemm<128,2>, cudaFuncAttributeMaxDynamicSharedMemorySize, SM128);
    cudaFuncSetAttribute(hgemm<64,3>,  cudaFuncAttributeMaxDynamicSharedMemorySize, SM64);

    // ---- 0) conversions ----
    f2h_k<<<NTOK*DM/1024, 256>>>(src, srch);
    {
        dim3 b(32,8);
        transpose_cvt<<<dim3(32,32),  b>>>(wq, wqTh, DM, DM);
        transpose_cvt<<<dim3(32,32),  b>>>(wk, wkTh, DM, DM);
        transpose_cvt<<<dim3(32,32),  b>>>(wv, wvTh, DM, DM);
        transpose_cvt<<<dim3(32,32),  b>>>(wo, woTh, DM, DM);
        transpose_cvt<<<dim3(128,32), b>>>(w1, w1Th, DM, DFF);   // -> [DFF, DM]
        transpose_cvt<<<dim3(32,128), b>>>(w2, w2Th, DFF, DM);   // -> [DM, DFF]
    }
    zero_k<<<NROWS/1024, 1024>>>(rsum);

    // ---- 1) QKV projections (fp16 out) ----
    {
        dim3 grid(DM/128, NTOK/128, 1);
        hgemm<128,1><<<grid,256,SM128>>>(srch, wqTh, bq, qh, nullptr,
            DM, DM, DM, DM, 0,0,0,0,0,0, 1.f, 0);
        hgemm<128,1><<<grid,256,SM128>>>(srch, wkTh, bk, kh, nullptr,
            DM, DM, DM, DM, 0,0,0,0,0,0, 1.f, 0);
        hgemm<128,1><<<grid,256,SM128>>>(srch, wvTh, bv, vh, nullptr,
            DM, DM, DM, DM, 0,0,0,0,0,0, 1.f, 0);
    }

    // ---- 2) E = exp(Q K^T / 8) fp16 + row sums ----
    {
        dim3 grid(SS/128, SS/128, BBATCH*NH);
        hgemm<128,2><<<grid,256,SM128>>>(qh, kh, nullptr, E, rsum,
            DK, DM, DM, SS,
            (long)SS*DM, DK,
            (long)SS*DM, DK,
            (long)NH*SS*SS, (long)SS*SS,
            0.125f, 0);
    }

    // ---- 3) V transpose per batch ----
    transpose_hh<<<dim3(DM/32, SS/32, BBATCH), dim3(32,8)>>>(vh, vth, SS, DM);

    // ---- 4) attn output = E / rowsum (fp32) ----
    norm_attn<<<NROWS, 256>>>(E, rsum, attnp);

    // ---- 5) ctx = (E/rowsum) @ V  (row scaling in epilogue) ----
    {
        dim3 grid(1, SS/128, BBATCH*NH);
        hgemm<64,3><<<grid,256,SM64>>>(E, vth, nullptr, ctxh, rsum,
            SS, SS, SS, DM,
            (long)NH*SS*SS, (long)SS*SS,
            (long)DM*SS, (long)DK*SS,
            (long)SS*DM, DK,
            1.f, 0);
    }

    // ---- 6) attn_out = ctx @ Wo + bo (fp32) ----
    {
        dim3 grid(DM/128, NTOK/128, 1);
        hgemm<128,0><<<grid,256,SM128>>>(ctxh, woTh, bo, t0, nullptr,
            DM, DM, DM, DM, 0,0,0,0,0,0, 1.f, 0);
    }

    // ---- 7) x1 = LN(src + attn_out)  (fp32 + fp16) ----
    add_ln_k<<<NTOK, 256>>>(src, t0, g1, be1, x1, x1h);

    // ---- 8) ff = relu(x1 @ W1 + b1) fp16 ----
    {
        dim3 grid(DFF/128, NTOK/128, 1);
        hgemm<128,1><<<grid,256,SM128>>>(x1h, w1Th, b1, ffh, nullptr,
            DM, DM, DM, DFF, 0,0,0,0,0,0, 1.f, 1);
    }

    // ---- 9) t0 = ff @ W2 + b2 (fp32) ----
    {
        dim3 grid(DM/128, NTOK/128, 1);
        hgemm<128,0><<<grid,256,SM128>>>(ffh, w2Th, b2, t0, nullptr,
            DFF, DFF, DFF, DM, 0,0,0,0,0,0, 1.f, 0);
    }

    // ---- 10) out = LN(x1 + t0) ----
    add_ln_k<<<NTOK, 256>>>(x1, t0, g2, be2, outp, nullptr);
}

// round 6
// speedup vs baseline: 1.7798x; 1.0071x over previous
#include <cuda_runtime.h>
#include <cuda_fp16.h>
#include <cstdint>

// ---------------- problem constants ----------------
#define BBATCH 2
#define SS 2048
#define DM 1024
#define NH 16
#define DK 64
#define DFF 4096
#define NTOK (BBATCH*SS)                  // 4096
#define OUT_ELEMS ((long)NTOK*DM)         // 4,194,304
#define NROWS (BBATCH*NH*SS)              // 65536 attention rows

// ---------------- scratch (device globals, allocation-free) ----------------
__device__ __half g_srch [NTOK*DM];
__device__ __half g_qkvh [(long)NTOK*3*DM];       // [tok][q|k|v]
__device__ __half g_vth  [NTOK*DM];               // V^T per batch: [B][DM][S]
__device__ __half g_E    [(long)BBATCH*NH*SS*SS]; // unnormalized exp(scores)
__device__ __half g_ctxh [NTOK*DM];
__device__ __half g_x1h  [NTOK*DM];
__device__ __half g_ffh  [NTOK*DFF];
__device__ __half g_wqkvT[3*DM*DM];
__device__ __half g_woTh [DM*DM];
__device__ __half g_w1Th [DM*DFF];
__device__ __half g_w2Th [DM*DFF];
__device__ float  g_t0   [NTOK*DM];
__device__ float  g_x1   [NTOK*DM];
__device__ float  g_rsum [NROWS];
__device__ float  g_bqkv [3*DM];

__device__ __forceinline__ uint32_t smem_u32(const void* p){
    uint32_t a;
    asm("{ .reg .u64 t; cvta.to.shared.u64 t, %1; cvt.u32.u64 %0, t; }" : "=r"(a) : "l"(p));
    return a;
}
__device__ __forceinline__ void cpa16(uint32_t dst, const void* src){
    asm volatile("cp.async.cg.shared.global [%0], [%1], 16;" :: "r"(dst), "l"(src));
}
__device__ __forceinline__ void cpa_commit(){
    asm volatile("cp.async.commit_group;" ::: "memory");
}
template<int N>
__device__ __forceinline__ void cpa_wait(){
    asm volatile("cp.async.wait_group %0;" :: "n"(N) : "memory");
}
#define MMA16816(d, a0,a1,a2,a3, b0,b1) \
    asm("mma.sync.aligned.m16n8k16.row.col.f32.f16.f16.f32 " \
        "{%0,%1,%2,%3}, {%4,%5,%6,%7}, {%8,%9}, {%0,%1,%2,%3};" \
        : "+f"(d[0]), "+f"(d[1]), "+f"(d[2]), "+f"(d[3]) \
        : "r"(a0), "r"(a1), "r"(a2), "r"(a3), "r"(b0), "r"(b1))

// ---------------------------------------------------------------------------
// fp16 mma.sync GEMM:  acc = A[M,K] * B[N,K]^T  (both K-major fp16)
// MODE 0: C fp32 = acc + bias (+relu) ; MODE 1: C fp16 = acc + bias (+relu)
// ---------------------------------------------------------------------------
template<int BN, int MODE>
__global__ void __launch_bounds__(256)
hgemm(const __half* __restrict__ A, const __half* __restrict__ B,
      const float* __restrict__ bias, void* __restrict__ Cv,
      int K, int lda, int ldb, int ldc, int relu)
{
    constexpr int BKH  = 32;
    constexpr int LDH  = 40;           // pitch halfs (20 words)
    constexpr int ST   = 3;
    constexpr int WN   = BN/2;
    constexpr int NT   = WN/8;
    constexpr int AIT  = 2;
    constexpr int BIT  = BN/64;
    constexpr int ASTG = 128*LDH;
    constexpr int BSTG = BN*LDH;

    extern __shared__ __half hs[];
    const uint32_t aU = smem_u32(hs);
    const uint32_t bU = smem_u32(hs + ST*ASTG);

    const int tid = threadIdx.x, wid = tid>>5, lane = tid&31;
    const int m0 = blockIdx.y*128, n0 = blockIdx.x*BN;
    A += (long)m0*lda;
    B += (long)n0*ldb;

    const int wm = (wid>>1)*32, wn = (wid&1)*WN;
    const int r4 = lane>>2, c4 = lane&3;

    float acc[2][NT][4];
    #pragma unroll
    for (int i = 0; i < 2; i++)
        #pragma unroll
        for (int j = 0; j < NT; j++)
            #pragma unroll
            for (int q = 0; q < 4; q++) acc[i][j][q] = 0.f;

    const int nch = K / BKH;

    #pragma unroll
    for (int s = 0; s < ST-1; s++){
        if (s < nch){
            const int k0 = s*BKH;
            #pragma unroll
            for (int i = 0; i < AIT; i++){
                int idx = i*256 + tid, r = idx>>2, sg = idx&3;
                cpa16(aU + (s*ASTG + r*LDH + sg*8)*2, A + (long)r*lda + k0 + sg*8);
            }
            #pragma unroll
            for (int i = 0; i < BIT; i++){
                int idx = i*256 + tid, r = idx>>2, sg = idx&3;
                cpa16(bU + (s*BSTG + r*LDH + sg*8)*2, B + (long)r*ldb + k0 + sg*8);
            }
        }
        cpa_commit();
    }

    for (int c = 0; c < nch; c++){
        cpa_wait<ST-2>();
        __syncthreads();

        if (c + ST-1 < nch){
            const int s = (c + ST-1) % ST;
            const int k0 = (c + ST-1)*BKH;
            #pragma unroll
            for (int i = 0; i < AIT; i++){
                int idx = i*256 + tid, r = idx>>2, sg = idx&3;
                cpa16(aU + (s*ASTG + r*LDH + sg*8)*2, A + (long)r*lda + k0 + sg*8);
            }
            #pragma unroll
            for (int i = 0; i < BIT; i++){
                int idx = i*256 + tid, r = idx>>2, sg = idx&3;
                cpa16(bU + (s*BSTG + r*LDH + sg*8)*2, B + (long)r*ldb + k0 + sg*8);
            }
        }
        cpa_commit();

        const uint32_t* aw = (const uint32_t*)(hs + (c % ST)*ASTG);
        const uint32_t* bw = (const uint32_t*)(hs + ST*ASTG + (c % ST)*BSTG);

        #pragma unroll
        for (int ks = 0; ks < 2; ks++){
            uint32_t bf[NT][2];
            #pragma unroll
            for (int nj = 0; nj < NT; nj++){
                const uint32_t* bp = bw + (wn + nj*8 + r4)*20 + ks*8 + c4;
                bf[nj][0] = bp[0];
                bf[nj][1] = bp[4];
            }
            #pragma unroll
            for (int mi = 0; mi < 2; mi++){
                const uint32_t* ap = aw + (wm + mi*16 + r4)*20 + ks*8 + c4;
                uint32_t a0 = ap[0], a1 = ap[160], a2 = ap[4], a3 = ap[164];
                #pragma unroll
                for (int nj = 0; nj < NT; nj++)
                    MMA16816(acc[mi][nj], a0,a1,a2,a3, bf[nj][0], bf[nj][1]);
            }
        }
    }

    #pragma unroll
    for (int mi = 0; mi < 2; mi++){
        const int row0 = m0 + wm + mi*16 + r4;
        #pragma unroll
        for (int nj = 0; nj < NT; nj++){
            const int col = n0 + wn + nj*8 + c4*2;
            float b0 = bias ? __ldg(&bias[col])   : 0.f;
            float b1 = bias ? __ldg(&bias[col+1]) : 0.f;
            float v0 = acc[mi][nj][0] + b0;
            float v1 = acc[mi][nj][1] + b1;
            float v2 = acc[mi][nj][2] + b0;
            float v3 = acc[mi][nj][3] + b1;
            if (relu){ v0=fmaxf(v0,0.f); v1=fmaxf(v1,0.f); v2=fmaxf(v2,0.f); v3=fmaxf(v3,0.f); }
            if (MODE == 0){
                float* C = (float*)Cv;
                *(float2*)&C[(long)row0*ldc + col]     = make_float2(v0,v1);
                *(float2*)&C[(long)(row0+8)*ldc + col] = make_float2(v2,v3);
            } else {
                __half* C = (__half*)Cv;
                *(__half2*)&C[(long)row0*ldc + col]     = __floats2half2_rn(v0,v1);
                *(__half2*)&C[(long)(row0+8)*ldc + col] = __floats2half2_rn(v2,v3);
            }
        }
    }
}

// ---------------------------------------------------------------------------
// Fused flash-style attention.
// grid: (1, 16 q-blocks, 32 (b,h)); 256 threads = 8 warps; warp owns 16 Q rows.
// Per 128-col K/V tile: S = Q K^T (tensor), E = exp(S/8) -> gmem fp16 +
// register A-fragments for ctx += E V (tensor). rowsum in registers.
// ---------------------------------------------------------------------------
__global__ void __launch_bounds__(256)
flash_attn(const __half* __restrict__ qkv,   // [NTOK][3*DM]
           const __half* __restrict__ vth,   // [B][DM][SS]
           __half* __restrict__ E,           // [B*NH][SS][SS]
           float* __restrict__ rsum,         // [B*NH*SS]
           __half* __restrict__ ctx)         // [NTOK][DM]
{
    constexpr int KPH = 72;    // K tile pitch (halfs), 36 words
    constexpr int VPH = 136;   // V tile pitch (halfs), 68 words
    constexpr int KSTG = 128*KPH;
    constexpr int VSTG = 64*VPH;

    extern __shared__ __half sh[];
    __half* KsB = sh;                 // [2][KSTG]
    __half* VsB = sh + 2*KSTG;        // [2][VSTG]
    const uint32_t kU = smem_u32(KsB);
    const uint32_t vU = smem_u32(VsB);

    const int tid = threadIdx.x, wid = tid>>5, lane = tid&31;
    const int r4 = lane>>2, c4 = lane&31&3;
    const int z = blockIdx.z, b = z>>4, h = z&15;
    const int srow0 = blockIdx.y*128 + wid*16;       // row within batch
    const long tok0 = (long)b*SS + srow0;

    // ---- Q fragments (resident) ----
    const __half* q0 = qkv + (tok0 + r4)*3*DM + h*64;
    const __half* q8 = q0 + 8*3*DM;
    uint32_t qa[4][4];
    #pragma unroll
    for (int ks = 0; ks < 4; ks++){
        qa[ks][0] = *(const uint32_t*)(q0 + ks*16 + 2*c4);
        qa[ks][1] = *(const uint32_t*)(q8 + ks*16 + 2*c4);
        qa[ks][2] = *(const uint32_t*)(q0 + ks*16 + 2*c4 + 8);
        qa[ks][3] = *(const uint32_t*)(q8 + ks*16 + 2*c4 + 8);
    }

    const __half* kbase = qkv + (long)b*SS*3*DM + DM + h*64;   // K section
    const __half* vbase = vth + ((long)b*DM + h*64)*SS;

    float ctxa[8][4];
    #pragma unroll
    for (int j = 0; j < 8; j++)
        #pragma unroll
        for (int q = 0; q < 4; q++) ctxa[j][q] = 0.f;
    float sumA = 0.f, sumB = 0.f;

    // tile loader
    auto load_tiles = [&](int t, int st){
        #pragma unroll
        for (int i = 0; i < 4; i++){
            int idx = i*256 + tid, r = idx>>3, sg = idx&7;
            cpa16(kU + (st*KSTG + r*KPH + sg*8)*2,
                  kbase + (long)(t*128 + r)*3*DM + sg*8);
        }
        #pragma unroll
        for (int i = 0; i < 4; i++){
            int idx = i*256 + tid, r = idx>>4, sg = idx&15;
            cpa16(vU + (st*VSTG + r*VPH + sg*8)*2,
                  vbase + (long)r*SS + t*128 + sg*8);
        }
    };

    load_tiles(0, 0);
    cpa_commit();

    for (int t = 0; t < 16; t++){
        const int st = t & 1;
        if (t+1 < 16){
            load_tiles(t+1, st^1);
            cpa_commit();
            cpa_wait<1>();
        } else {
            cpa_wait<0>();
        }
        __syncthreads();

        const __half* Ks = KsB + st*KSTG;
        const __half* Vs = VsB + st*VSTG;

        // ---- S = Q K^T ----
        float sacc[16][4];
        #pragma unroll
        for (int nj = 0; nj < 16; nj++)
            #pragma unroll
            for (int q = 0; q < 4; q++) sacc[nj][q] = 0.f;

        #pragma unroll
        for (int ks = 0; ks < 4; ks++){
            #pragma unroll
            for (int nj = 0; nj < 16; nj++){
                const uint32_t* bp = (const uint32_t*)Ks + (nj*8 + r4)*36 + ks*8 + c4;
                MMA16816(sacc[nj], qa[ks][0], qa[ks][1], qa[ks][2], qa[ks][3],
                         bp[0], bp[4]);
            }
        }

        // ---- E = exp(S/8): store + keep register fragments ----
        uint32_t ehA[16], ehB[16];
        __half* erow = E + ((long)z*SS + srow0 + r4)*SS + t*128 + 2*c4;
        #pragma unroll
        for (int nj = 0; nj < 16; nj++){
            float e0 = __expf(sacc[nj][0]*0.125f);
            float e1 = __expf(sacc[nj][1]*0.125f);
            float e2 = __expf(sacc[nj][2]*0.125f);
            float e3 = __expf(sacc[nj][3]*0.125f);
            sumA += e0 + e1;
            sumB += e2 + e3;
            __half2 hA = __floats2half2_rn(e0, e1);
            __half2 hB = __floats2half2_rn(e2, e3);
            ehA[nj] = *(uint32_t*)&hA;
            ehB[nj] = *(uint32_t*)&hB;
            *(__half2*)(erow + nj*8)          = hA;
            *(__half2*)(erow + nj*8 + 8*SS)   = hB;
        }

        // ---- ctx += E V ----
        #pragma unroll
        for (int ks2 = 0; ks2 < 8; ks2++){
            #pragma unroll
            for (int njc = 0; njc < 8; njc++){
                const uint32_t* bp = (const uint32_t*)Vs + (njc*8 + r4)*68 + ks2*8 + c4;
                MMA16816(ctxa[njc], ehA[2*ks2], ehB[2*ks2], ehA[2*ks2+1], ehB[2*ks2+1],
                         bp[0], bp[4]);
            }
        }
        __syncthreads();
    }

    // ---- rowsum reduce (quad) + write ----
    sumA += __shfl_xor_sync(0xffffffffu, sumA, 1);
    sumA += __shfl_xor_sync(0xffffffffu, sumA, 2);
    sumB += __shfl_xor_sync(0xffffffffu, sumB, 1);
    sumB += __shfl_xor_sync(0xffffffffu, sumB, 2);
    if (c4 == 0){
        rsum[(long)z*SS + srow0 + r4]     = sumA;
        rsum[(long)z*SS + srow0 + r4 + 8] = sumB;
    }
    const float iA = __fdividef(1.f, sumA);
    const float iB = __fdividef(1.f, sumB);

    __half* crow = ctx + (tok0 + r4)*DM + h*64 + 2*c4;
    #pragma unroll
    for (int njc = 0; njc < 8; njc++){
        *(__half2*)(crow + njc*8)          = __floats2half2_rn(ctxa[njc][0]*iA, ctxa[njc][1]*iA);
        *(__half2*)(crow + njc*8 + 8*DM)   = __floats2half2_rn(ctxa[njc][2]*iB, ctxa[njc][3]*iB);
    }
}

// ---------------------------------------------------------------------------
__global__ void f2h_k(const float* __restrict__ in, __half* __restrict__ out){
    long i = ((long)blockIdx.x*256 + threadIdx.x)*4;
    float4 v = *(const float4*)(in + i);
    *(__half2*)(out + i)     = __floats2half2_rn(v.x, v.y);
    *(__half2*)(out + i + 2) = __floats2half2_rn(v.z, v.w);
}

__global__ void concat_bias(const float* __restrict__ bq, const float* __restrict__ bk,
                            const float* __restrict__ bv, float* __restrict__ o){
    int i = blockIdx.x*256 + threadIdx.x;
    o[i] = (i < DM) ? bq[i] : (i < 2*DM ? bk[i-DM] : bv[i-2*DM]);
}

// transpose fp32 -> fp16: out[c*ldo + r] = in[r*C + c]   (ldo = R)
__global__ void transpose_cvt(const float* __restrict__ in, __half* __restrict__ out,
                              int R, int C){
    __shared__ float t[32][33];
    const int c0 = blockIdx.x*32, r0 = blockIdx.y*32;
    #pragma unroll
    for (int i = threadIdx.y; i < 32; i += 8)
        t[i][threadIdx.x] = in[(long)(r0+i)*C + c0 + threadIdx.x];
    __syncthreads();
    #pragma unroll
    for (int i = threadIdx.y; i < 32; i += 8)
        out[(long)(c0+i)*R + r0 + threadIdx.x] = __float2half_rn(t[threadIdx.x][i]);
}

// V^T from qkv buffer: vth[b][d][s] = qkv[(b*SS+s)*3072 + 2048 + d]
__global__ void transpose_v(const __half* __restrict__ qkv, __half* __restrict__ vt){
    __shared__ __half t[32][34];
    const int b = blockIdx.z;
    const int d0 = blockIdx.x*32, s0 = blockIdx.y*32;
    #pragma unroll
    for (int i = threadIdx.y; i < 32; i += 8)
        t[i][threadIdx.x] = qkv[((long)b*SS + s0 + i)*(3*DM) + 2*DM + d0 + threadIdx.x];
    __syncthreads();
    #pragma unroll
    for (int i = threadIdx.y; i < 32; i += 8)
        vt[((long)b*DM + d0 + i)*SS + s0 + threadIdx.x] = t[threadIdx.x][i];
}

// attn P (fp32, mandatory output) = E (fp16) / rowsum
__global__ void norm_attn(const __half* __restrict__ E, const float* __restrict__ rsum,
                          float* __restrict__ P){
    const long row = blockIdx.x;
    const __half2* e = (const __half2*)(E + row*(long)SS);
    float2* p = (float2*)(P + row*(long)SS);
    const float inv = __fdividef(1.f, __ldg(&rsum[row]));
    const int t = threadIdx.x;
    #pragma unroll
    for (int i = 0; i < 4; i++){
        float2 f = __half22float2(e[t + i*256]);
        f.x *= inv; f.y *= inv;
        p[t + i*256] = f;
    }
}

// x1 = LN(a + r); writes fp32 and (optionally) fp16
__global__ void add_ln_k(const float* __restrict__ a, const float* __restrict__ r,
                         const float* __restrict__ g, const float* __restrict__ be,
                         float* __restrict__ o, __half* __restrict__ oh)
{
    const long row = blockIdx.x;
    const int t = threadIdx.x;
    float4 x = ((const float4*)(a + row*DM))[t];
    float4 y = ((const float4*)(r + row*DM))[t];
    x.x += y.x; x.y += y.y; x.z += y.z; x.w += y.w;

    __shared__ float rs[256], rq[256];
    rs[t] = x.x+x.y+x.z+x.w;
    rq[t] = x.x*x.x + x.y*x.y + x.z*x.z + x.w*x.w;
    __syncthreads();
    for (int s = 128; s > 0; s >>= 1){
        if (t < s){ rs[t] += rs[t+s]; rq[t] += rq[t+s]; }
        __syncthreads();
    }
    const float mu  = rs[0] * (1.f/DM);
    const float var = rq[0] * (1.f/DM) - mu*mu;
    const float rst = rsqrtf(var + 1e-5f);

    float4 gg = ((const float4*)g)[t];
    float4 bb = ((const float4*)be)[t];
    float4 out;
    out.x = (x.x-mu)*rst*gg.x + bb.x;
    out.y = (x.y-mu)*rst*gg.y + bb.y;
    out.z = (x.z-mu)*rst*gg.z + bb.z;
    out.w = (x.w-mu)*rst*gg.w + bb.w;
    ((float4*)(o + row*DM))[t] = out;
    if (oh){
        *(__half2*)(oh + row*DM + t*4)     = __floats2half2_rn(out.x, out.y);
        *(__half2*)(oh + row*DM + t*4 + 2) = __floats2half2_rn(out.z, out.w);
    }
}

// ---------------------------------------------------------------------------

extern "C" void kernel_launch(void* const* d_in, const int* in_sizes, int n_in,
                              void* d_out, int out_size)
{
    const float* src = (const float*)d_in[0];
    const float* wq  = (const float*)d_in[1];
    const float* bq  = (const float*)d_in[2];
    const float* wk  = (const float*)d_in[3];
    const float* bk  = (const float*)d_in[4];
    const float* wv  = (const float*)d_in[5];
    const float* bv  = (const float*)d_in[6];
    const float* wo  = (const float*)d_in[7];
    const float* bo  = (const float*)d_in[8];
    const float* w1  = (const float*)d_in[9];
    const float* b1  = (const float*)d_in[10];
    const float* w2  = (const float*)d_in[11];
    const float* b2  = (const float*)d_in[12];
    const float* g1  = (const float*)d_in[13];
    const float* be1 = (const float*)d_in[14];
    const float* g2  = (const float*)d_in[15];
    const float* be2 = (const float*)d_in[16];

    float* outp  = (float*)d_out;
    float* attnp = (float*)d_out + OUT_ELEMS;

    __half *srch,*qkvh,*vth,*E,*ctxh,*x1h,*ffh,*wqkvT,*woTh,*w1Th,*w2Th;
    float *t0,*x1,*rsum,*bqkv;
    cudaGetSymbolAddress((void**)&srch,  g_srch);
    cudaGetSymbolAddress((void**)&qkvh,  g_qkvh);
    cudaGetSymbolAddress((void**)&vth,   g_vth);
    cudaGetSymbolAddress((void**)&E,     g_E);
    cudaGetSymbolAddress((void**)&ctxh,  g_ctxh);
    cudaGetSymbolAddress((void**)&x1h,   g_x1h);
    cudaGetSymbolAddress((void**)&ffh,   g_ffh);
    cudaGetSymbolAddress((void**)&wqkvT, g_wqkvT);
    cudaGetSymbolAddress((void**)&woTh,  g_woTh);
    cudaGetSymbolAddress((void**)&w1Th,  g_w1Th);
    cudaGetSymbolAddress((void**)&w2Th,  g_w2Th);
    cudaGetSymbolAddress((void**)&t0,    g_t0);
    cudaGetSymbolAddress((void**)&x1,    g_x1);
    cudaGetSymbolAddress((void**)&rsum,  g_rsum);
    cudaGetSymbolAddress((void**)&bqkv,  g_bqkv);

    const int SMG = 3*(128*40 + 128*40)*2;                    // 61440
    const int SMF = (2*128*72 + 2*64*136)*2;                  // 71680
    cudaFuncSetAttribute(hgemm<128,0>, cudaFuncAttributeMaxDynamicSharedMemorySize, SMG);
    cudaFuncSetAttribute(hgemm<128,1>, cudaFuncAttributeMaxDynamicSharedMemorySize, SMG);
    cudaFuncSetAttribute(flash_attn,   cudaFuncAttributeMaxDynamicSharedMemorySize, SMF);

    // ---- 0) conversions / packing ----
    f2h_k<<<NTOK*DM/1024, 256>>>(src, srch);
    {
        dim3 b(32,8);
        transpose_cvt<<<dim3(32,32),  b>>>(wq, wqkvT,              DM, DM);
        transpose_cvt<<<dim3(32,32),  b>>>(wk, wqkvT + DM*DM,      DM, DM);
        transpose_cvt<<<dim3(32,32),  b>>>(wv, wqkvT + 2*DM*DM,    DM, DM);
        transpose_cvt<<<dim3(32,32),  b>>>(wo, woTh,               DM, DM);
        transpose_cvt<<<dim3(128,32), b>>>(w1, w1Th, DM, DFF);
        transpose_cvt<<<dim3(32,128), b>>>(w2, w2Th, DFF, DM);
    }
    concat_bias<<<3*DM/256, 256>>>(bq, bk, bv, bqkv);

    // ---- 1) fused QKV projection: [4096,3072] ----
    hgemm<128,1><<<dim3(3*DM/128, NTOK/128), 256, SMG>>>(
        srch, wqkvT, bqkv, qkvh, DM, DM, DM, 3*DM, 0);

    // ---- 2) V^T per batch ----
    transpose_v<<<dim3(DM/32, SS/32, BBATCH), dim3(32,8)>>>(qkvh, vth);

    // ---- 3) fused attention: E, rowsum, ctx ----
    flash_attn<<<dim3(1, SS/128, BBATCH*NH), 256, SMF>>>(qkvh, vth, E, rsum, ctxh);

    // ---- 4) attn output (fp32) = E / rowsum ----
    norm_attn<<<NROWS, 256>>>(E, rsum, attnp);

    // ---- 5) attn_out = ctx @ Wo + bo (fp32) ----
    hgemm<128,0><<<dim3(DM/128, NTOK/128), 256, SMG>>>(
        ctxh, woTh, bo, t0, DM, DM, DM, DM, 0);

    // ---- 6) x1 = LN(src + attn_out) ----
    add_ln_k<<<NTOK, 256>>>(src, t0, g1, be1, x1, x1h);

    // ---- 7) ff = relu(x1 @ W1 + b1) ----
    hgemm<128,1><<<dim3(DFF/128, NTOK/128), 256, SMG>>>(
        x1h, w1Th, b1, ffh, DM, DM, DM, DFF, 1);

    // ---- 8) t0 = ff @ W2 + b2 ----
    hgemm<128,0><<<dim3(DM/128, NTOK/128), 256, SMG>>>(
        ffh, w2Th, b2, t0, DFF, DFF, DFF, DM, 0);

    // ---- 9) out = LN(x1 + t0) ----
    add_ln_k<<<NTOK, 256>>>(x1, t0, g2, be2, outp, nullptr);
}